// round 10
// baseline (speedup 1.0000x reference)
#include <cuda_runtime.h>
#include <cstdint>

// FISTA denoiser, packed f32x2, ghost-boundary uniform 5-point stencil,
// y spilled to shared memory for occupancy-5.
// One warp = two rows; each u64 register packs (row0[i], row1[i]).
// y lives in __shared__ [elem][tid] (exclusive per-thread column -> no syncs,
// no bank conflicts); reloaded once per element per iteration via LDS.64.

#define LAM   10.0f
#define NIT   100
#define ROWN  512
#define EPL   16
#define TPB   128

typedef unsigned long long u64;

__device__ __forceinline__ u64 pk(float lo, float hi) {
    u64 r; asm("mov.b64 %0, {%1,%2};" : "=l"(r) : "f"(lo), "f"(hi)); return r;
}
__device__ __forceinline__ void upk(u64 v, float& lo, float& hi) {
    asm("mov.b64 {%0,%1}, %2;" : "=f"(lo), "=f"(hi) : "l"(v));
}
__device__ __forceinline__ u64 fma2(u64 a, u64 b, u64 c) {
    u64 d; asm("fma.rn.f32x2 %0, %1, %2, %3;" : "=l"(d) : "l"(a), "l"(b), "l"(c)); return d;
}
__device__ __forceinline__ u64 add2(u64 a, u64 b) {
    u64 d; asm("add.rn.f32x2 %0, %1, %2;" : "=l"(d) : "l"(a), "l"(b)); return d;
}
__device__ __forceinline__ u64 mul2(u64 a, u64 b) {
    u64 d; asm("mul.rn.f32x2 %0, %1, %2;" : "=l"(d) : "l"(a), "l"(b)); return d;
}
__device__ __forceinline__ u64 bc(float f) { return pk(f, f); }

// volatile shared ld/st (asm volatile prevents hoisting loop-invariant loads
// back into registers, which would defeat the register savings)
__device__ __forceinline__ u64 lds64(unsigned a) {
    u64 r; asm volatile("ld.shared.b64 %0, [%1];" : "=l"(r) : "r"(a)); return r;
}
__device__ __forceinline__ void sts64(unsigned a, u64 v) {
    asm volatile("st.shared.b64 [%0], %1;" :: "r"(a), "l"(v));
}

// A = 1/(1+16*LAM) = 2*step ; B = LAM/(1+16*LAM) = 2*LAM*step
#define C_A (1.0f / (1.0f + 16.0f * LAM))
#define C_B (LAM  / (1.0f + 16.0f * LAM))

// ---- compile-time FISTA momentum table, pre-broadcast as u64 f32x2 pairs ----
constexpr u64 bcast_bits(float f) {
    unsigned b = __builtin_bit_cast(unsigned, f);
    return ((u64)b << 32) | (u64)b;
}
struct MTab { u64 m1p[NIT]; u64 mn[NIT]; };
constexpr MTab make_mtab() {
    MTab t{};
    double tt = 1.0;
    for (int i = 0; i < NIT; i++) {
        double s = 1.0 + 4.0 * tt * tt;
        double r = s;                         // Newton sqrt
        for (int k = 0; k < 64; k++) r = 0.5 * (r + s / r);
        double tn = 0.5 * (1.0 + r);
        double m  = (tt - 1.0) / tn;
        t.m1p[i] = bcast_bits((float)(1.0 + m));
        t.mn[i]  = bcast_bits((float)(-m));
        tt = tn;
    }
    return t;
}
__constant__ MTab c_mtab = make_mtab();

// One FISTA solve. ybase: smem address of this thread's y[0] (stride 1024B
// between elements). x: output (packed registers).
__device__ __forceinline__ void solve2(unsigned ybase,
                                       u64* __restrict__ x,
                                       int lane)
{
    const unsigned FULL = 0xffffffffu;
    const u64 C0  = bc(1.0f - C_A - 6.0f * C_B);   // center tap
    const u64 C1  = bc(4.0f * C_B);                // +/-1 taps
    const u64 C2  = bc(-C_B);                      // +/-2 taps
    const u64 CA  = bc(C_A);                       // data-term coefficient
    const u64 NEG1 = bc(-1.0f);

    u64 z[EPL];
    #pragma unroll
    for (int i = 0; i < EPL; i++) {
        u64 yi = lds64(ybase + i * (TPB * 8));
        x[i] = yi; z[i] = yi;                      // proj(y)=y on [0,y]
    }

    const bool l0 = (lane == 0), l31 = (lane == 31);

    for (int it = 0; it < NIT; ++it) {
        // 64-bit halo shuffles
        u64 zm2 = __shfl_up_sync  (FULL, z[EPL - 2], 1);
        u64 zm1 = __shfl_up_sync  (FULL, z[EPL - 1], 1);
        u64 zp0 = __shfl_down_sync(FULL, z[0], 1);
        u64 zp1 = __shfl_down_sync(FULL, z[1], 1);

        // ghost values making the uniform stencil exact at the boundaries
        {
            u64 dl  = fma2(NEG1, z[1], z[0]);              // z0 - z1
            u64 g1  = add2(z[0], dl);                      // 2 z0 - z1
            u64 g2  = add2(g1,  dl);                       // 3 z0 - 2 z1
            u64 dr  = fma2(NEG1, z[EPL - 2], z[EPL - 1]);  // z15 - z14
            u64 g3  = add2(z[EPL - 1], dr);                // 2 z15 - z14
            u64 g4  = add2(g3, dr);                        // 3 z15 - 2 z14
            zm1 = l0  ? g1 : zm1;
            zm2 = l0  ? g2 : zm2;
            zp0 = l31 ? g3 : zp0;
            zp1 = l31 ? g4 : zp1;
        }

        // ze[k] = z_ext[16*lane - 2 + k], k = 0..19  (snapshot of z)
        u64 ze[EPL + 4];
        ze[0] = zm2; ze[1] = zm1;
        #pragma unroll
        for (int i = 0; i < EPL; i++) ze[2 + i] = z[i];
        ze[EPL + 2] = zp0; ze[EPL + 3] = zp1;

        // momentum coefficients (pre-broadcast u64 pairs, one LDC.64 each)
        const u64 M1P = c_mtab.m1p[it];
        const u64 MN  = c_mtab.mn[it];

        // fully uniform, branch-free element loop
        #pragma unroll
        for (int i = 0; i < EPL; i++) {
            u64 yi = lds64(ybase + i * (TPB * 8));

            // v = CA*y + C0*z + C1*(z[-1]+z[+1]) + C2*(z[-2]+z[+2])
            u64 s1 = add2(ze[i + 1], ze[i + 3]);
            u64 s2 = add2(ze[i],     ze[i + 4]);
            u64 v  = fma2(CA, yi,
                       fma2(C0, ze[i + 2],
                         fma2(C1, s1, mul2(C2, s2))));

            // clamp onto [0, y] — scalar FMNMX pairs on alu pipe
            float vl, vh, yl, yh;
            upk(v, vl, vh);
            upk(yi, yl, yh);
            float xl = fminf(fmaxf(vl, 0.0f), yl);
            float xh = fminf(fmaxf(vh, 0.0f), yh);
            u64 xn = pk(xl, xh);

            // z_new = (1+m) x_new - m x_old
            u64 zn = fma2(M1P, xn, mul2(MN, x[i]));
            x[i] = xn;
            z[i] = zn;
        }
    }
}

__global__ void __launch_bounds__(TPB, 5)
fista_denoise10_kernel(const float* __restrict__ in, float* __restrict__ out, int npairs)
{
    __shared__ u64 ysh[EPL][TPB];

    const int tid   = threadIdx.x;
    const int gwarp = (int)((blockIdx.x * (unsigned)blockDim.x + tid) >> 5);
    const int lane  = tid & 31;
    if (gwarp >= npairs) return;   // whole warp exits together

    const unsigned ybase =
        (unsigned)__cvta_generic_to_shared(&ysh[0][tid]);

    const float* r0 = in + (size_t)(2 * gwarp) * ROWN + lane * EPL;
    const float* r1 = r0 + ROWN;

    // pack input pair-of-rows and stage y into smem (exclusive per-thread column)
    #pragma unroll
    for (int v = 0; v < EPL / 4; v++) {
        float4 a = reinterpret_cast<const float4*>(r0)[v];
        float4 b = reinterpret_cast<const float4*>(r1)[v];
        sts64(ybase + (4 * v + 0) * (TPB * 8), pk(a.x, b.x));
        sts64(ybase + (4 * v + 1) * (TPB * 8), pk(a.y, b.y));
        sts64(ybase + (4 * v + 2) * (TPB * 8), pk(a.z, b.z));
        sts64(ybase + (4 * v + 3) * (TPB * 8), pk(a.w, b.w));
    }

    u64 x[EPL];
    solve2(ybase, x, lane);                   // pass 1: y = input

    #pragma unroll
    for (int i = 0; i < EPL; i++)             // pass 2 data: y = pass-1 output
        sts64(ybase + i * (TPB * 8), x[i]);
    solve2(ybase, x, lane);

    float* w0 = out + (size_t)(2 * gwarp) * ROWN + lane * EPL;
    float* w1 = w0 + ROWN;
    #pragma unroll
    for (int v = 0; v < EPL / 4; v++) {
        float4 a, b;
        upk(x[4 * v + 0], a.x, b.x);
        upk(x[4 * v + 1], a.y, b.y);
        upk(x[4 * v + 2], a.z, b.z);
        upk(x[4 * v + 3], a.w, b.w);
        reinterpret_cast<float4*>(w0)[v] = a;
        reinterpret_cast<float4*>(w1)[v] = b;
    }
}

extern "C" void kernel_launch(void* const* d_in, const int* in_sizes, int n_in,
                              void* d_out, int out_size)
{
    const float* in = (const float*)d_in[0];
    float* out = (float*)d_out;
    const int nelem  = in_sizes[0];           // 32*512*512
    const int nrows  = nelem / ROWN;          // 16384
    const int npairs = nrows / 2;             // 8192 warps
    const int warps_per_block = TPB / 32;     // 4
    const int nblocks = (npairs + warps_per_block - 1) / warps_per_block;
    fista_denoise10_kernel<<<nblocks, TPB>>>(in, out, npairs);
}

// round 11
// speedup vs baseline: 1.1124x; 1.1124x over previous
#include <cuda_runtime.h>
#include <cstdint>

// FISTA denoiser, packed f32x2, ghost-boundary uniform 5-point stencil,
// A*y hoisted into registers, y in smem (clamp-only, late-chain LDS.64).
// One warp = two rows; each u64 register packs (row0[i], row1[i]).

#define LAM   10.0f
#define NIT   100
#define ROWN  512
#define EPL   16
#define TPB   128

typedef unsigned long long u64;

__device__ __forceinline__ u64 pk(float lo, float hi) {
    u64 r; asm("mov.b64 %0, {%1,%2};" : "=l"(r) : "f"(lo), "f"(hi)); return r;
}
__device__ __forceinline__ void upk(u64 v, float& lo, float& hi) {
    asm("mov.b64 {%0,%1}, %2;" : "=f"(lo), "=f"(hi) : "l"(v));
}
__device__ __forceinline__ u64 fma2(u64 a, u64 b, u64 c) {
    u64 d; asm("fma.rn.f32x2 %0, %1, %2, %3;" : "=l"(d) : "l"(a), "l"(b), "l"(c)); return d;
}
__device__ __forceinline__ u64 add2(u64 a, u64 b) {
    u64 d; asm("add.rn.f32x2 %0, %1, %2;" : "=l"(d) : "l"(a), "l"(b)); return d;
}
__device__ __forceinline__ u64 mul2(u64 a, u64 b) {
    u64 d; asm("mul.rn.f32x2 %0, %1, %2;" : "=l"(d) : "l"(a), "l"(b)); return d;
}
__device__ __forceinline__ u64 bc(float f) { return pk(f, f); }

__device__ __forceinline__ u64 lds64(unsigned a) {
    u64 r; asm volatile("ld.shared.b64 %0, [%1];" : "=l"(r) : "r"(a)); return r;
}
__device__ __forceinline__ void sts64(unsigned a, u64 v) {
    asm volatile("st.shared.b64 [%0], %1;" :: "r"(a), "l"(v));
}

// A = 1/(1+16*LAM) = 2*step ; B = LAM/(1+16*LAM) = 2*LAM*step
#define C_A (1.0f / (1.0f + 16.0f * LAM))
#define C_B (LAM  / (1.0f + 16.0f * LAM))

// ---- compile-time FISTA momentum table, pre-broadcast as u64 f32x2 pairs ----
constexpr u64 bcast_bits(float f) {
    unsigned b = __builtin_bit_cast(unsigned, f);
    return ((u64)b << 32) | (u64)b;
}
struct MTab { u64 m1p[NIT]; u64 mn[NIT]; };
constexpr MTab make_mtab() {
    MTab t{};
    double tt = 1.0;
    for (int i = 0; i < NIT; i++) {
        double s = 1.0 + 4.0 * tt * tt;
        double r = s;                         // Newton sqrt
        for (int k = 0; k < 64; k++) r = 0.5 * (r + s / r);
        double tn = 0.5 * (1.0 + r);
        double m  = (tt - 1.0) / tn;
        t.m1p[i] = bcast_bits((float)(1.0 + m));
        t.mn[i]  = bcast_bits((float)(-m));
        tt = tn;
    }
    return t;
}
__constant__ MTab c_mtab = make_mtab();

// One FISTA solve. y is in smem at ybase (stride TPB*8 between elements;
// clamp-only use). ay[] = C_A * y in registers. x: in/out packed state
// (on entry: x == y, the projected start point).
__device__ __forceinline__ void solve2(unsigned ybase,
                                       u64* __restrict__ x,
                                       int lane)
{
    const unsigned FULL = 0xffffffffu;
    const u64 C0  = bc(1.0f - C_A - 6.0f * C_B);   // center tap
    const u64 C1  = bc(4.0f * C_B);                // +/-1 taps
    const u64 C2  = bc(-C_B);                      // +/-2 taps
    const u64 CA  = bc(C_A);
    const u64 NEG1 = bc(-1.0f);

    u64 ay[EPL], z[EPL];
    #pragma unroll
    for (int i = 0; i < EPL; i++) {
        ay[i] = mul2(CA, x[i]);                    // x == y at entry
        z[i]  = x[i];
    }

    const bool l0 = (lane == 0), l31 = (lane == 31);

    for (int it = 0; it < NIT; ++it) {
        // 64-bit halo shuffles
        u64 zm2 = __shfl_up_sync  (FULL, z[EPL - 2], 1);
        u64 zm1 = __shfl_up_sync  (FULL, z[EPL - 1], 1);
        u64 zp0 = __shfl_down_sync(FULL, z[0], 1);
        u64 zp1 = __shfl_down_sync(FULL, z[1], 1);

        // ghost values making the uniform stencil exact at the boundaries
        {
            u64 dl  = fma2(NEG1, z[1], z[0]);              // z0 - z1
            u64 g1  = add2(z[0], dl);                      // 2 z0 - z1
            u64 g2  = add2(g1,  dl);                       // 3 z0 - 2 z1
            u64 dr  = fma2(NEG1, z[EPL - 2], z[EPL - 1]);  // z15 - z14
            u64 g3  = add2(z[EPL - 1], dr);                // 2 z15 - z14
            u64 g4  = add2(g3, dr);                        // 3 z15 - 2 z14
            zm1 = l0  ? g1 : zm1;
            zm2 = l0  ? g2 : zm2;
            zp0 = l31 ? g3 : zp0;
            zp1 = l31 ? g4 : zp1;
        }

        // ze[k] = z_ext[16*lane - 2 + k], k = 0..19  (snapshot of z)
        u64 ze[EPL + 4];
        ze[0] = zm2; ze[1] = zm1;
        #pragma unroll
        for (int i = 0; i < EPL; i++) ze[2 + i] = z[i];
        ze[EPL + 2] = zp0; ze[EPL + 3] = zp1;

        // momentum coefficients (pre-broadcast u64 pairs, one LDC.64 each)
        const u64 M1P = c_mtab.m1p[it];
        const u64 MN  = c_mtab.mn[it];

        // fully uniform, branch-free element loop (5 packed ops + clamp + 2)
        #pragma unroll
        for (int i = 0; i < EPL; i++) {
            // v = ay + C0*z + C1*(z[-1]+z[+1]) + C2*(z[-2]+z[+2])
            u64 s1 = add2(ze[i + 1], ze[i + 3]);
            u64 s2 = add2(ze[i],     ze[i + 4]);
            u64 v  = fma2(C0, ze[i + 2],
                       fma2(C1, s1,
                         fma2(C2, s2, ay[i])));

            // clamp onto [0, y] — y read late from smem, scalar FMNMX pairs
            u64 yi = lds64(ybase + i * (TPB * 8));
            float vl, vh, yl, yh;
            upk(v, vl, vh);
            upk(yi, yl, yh);
            float xl = fminf(fmaxf(vl, 0.0f), yl);
            float xh = fminf(fmaxf(vh, 0.0f), yh);
            u64 xn = pk(xl, xh);

            // z_new = (1+m) x_new - m x_old
            u64 zn = fma2(M1P, xn, mul2(MN, x[i]));
            x[i] = xn;
            z[i] = zn;
        }
    }
}

__global__ void __launch_bounds__(TPB, 4)
fista_denoise11_kernel(const float* __restrict__ in, float* __restrict__ out, int npairs)
{
    __shared__ u64 ysh[EPL][TPB];

    const int tid   = threadIdx.x;
    const int gwarp = (int)((blockIdx.x * (unsigned)blockDim.x + tid) >> 5);
    const int lane  = tid & 31;
    if (gwarp >= npairs) return;   // whole warp exits together

    const unsigned ybase = (unsigned)__cvta_generic_to_shared(&ysh[0][tid]);

    const float* r0 = in + (size_t)(2 * gwarp) * ROWN + lane * EPL;
    const float* r1 = r0 + ROWN;

    // pack input pair-of-rows into x registers and stage y into smem
    u64 x[EPL];
    #pragma unroll
    for (int v = 0; v < EPL / 4; v++) {
        float4 a = reinterpret_cast<const float4*>(r0)[v];
        float4 b = reinterpret_cast<const float4*>(r1)[v];
        x[4 * v + 0] = pk(a.x, b.x);
        x[4 * v + 1] = pk(a.y, b.y);
        x[4 * v + 2] = pk(a.z, b.z);
        x[4 * v + 3] = pk(a.w, b.w);
    }
    #pragma unroll
    for (int i = 0; i < EPL; i++) sts64(ybase + i * (TPB * 8), x[i]);

    solve2(ybase, x, lane);                   // pass 1: y = input

    #pragma unroll
    for (int i = 0; i < EPL; i++)             // pass 2 data: y = pass-1 output
        sts64(ybase + i * (TPB * 8), x[i]);
    solve2(ybase, x, lane);

    float* w0 = out + (size_t)(2 * gwarp) * ROWN + lane * EPL;
    float* w1 = w0 + ROWN;
    #pragma unroll
    for (int v = 0; v < EPL / 4; v++) {
        float4 a, b;
        upk(x[4 * v + 0], a.x, b.x);
        upk(x[4 * v + 1], a.y, b.y);
        upk(x[4 * v + 2], a.z, b.z);
        upk(x[4 * v + 3], a.w, b.w);
        reinterpret_cast<float4*>(w0)[v] = a;
        reinterpret_cast<float4*>(w1)[v] = b;
    }
}

extern "C" void kernel_launch(void* const* d_in, const int* in_sizes, int n_in,
                              void* d_out, int out_size)
{
    const float* in = (const float*)d_in[0];
    float* out = (float*)d_out;
    const int nelem  = in_sizes[0];           // 32*512*512
    const int nrows  = nelem / ROWN;          // 16384
    const int npairs = nrows / 2;             // 8192 warps
    const int warps_per_block = TPB / 32;     // 4
    const int nblocks = (npairs + warps_per_block - 1) / warps_per_block;
    fista_denoise11_kernel<<<nblocks, TPB>>>(in, out, npairs);
}